// round 17
// baseline (speedup 1.0000x reference)
#include <cuda_runtime.h>
#include <stdint.h>

// ---------------- problem constants ----------------
// SPARSE_SHAPE (468,468,1), WINDOW (12,12,1), BATCH 4
// _NX=_NY=40, _NZ=2 ; win_z==0 always ; full_win = 2*compact
// compact win id = b*1600 + wx*40 + wy  in [0, 6400)
#define NWc   6400
#define CAP   512               // max voxels per window (uniform data: ~49 mean)
#define MAXN  327680
#define FULLM 0xFFFFFFFFu
#define KLOG  0.4152410118609203f   // 4*log2(1e4)/128

// ---------------- static scratch (no allocations; zero-initialized) ---------
// g_cnt0/g_cnt1 are zero at load and restored to zero by the wrank kernels
// each replay (each block resets the counter it consumed).
__device__ int           g_cnt0[NWc];
__device__ int           g_cnt1[NWc];
__device__ int           g_bkt0[NWc * CAP];
__device__ int           g_bkt1[NWc * CAP];
__device__ int           g_winc0[MAXN];
__device__ int           g_winc1[MAXN];
__device__ int           g_inner0[MAXN];
__device__ int           g_inner1[MAXN];
__device__ signed char   g_dl0[MAXN];
__device__ signed char   g_dl1[MAXN];
__device__ unsigned char g_keep0[MAXN];
__device__ unsigned char g_keepF[MAXN];

__device__ __forceinline__ void lvl_target(int n, int& lvl, int& target) {
    if (n < 16)      { lvl = 0; target = 16; }
    else if (n < 32) { lvl = 1; target = 32; }
    else if (n < 64) { lvl = 2; target = 64; }
    else             { lvl = 3; target = 144; }
}

// ---------------- phase 1: window ids + bucket scatter (round 0) ------------
__global__ void k_scatter0(const int* __restrict__ coords, int N) {
    int i = blockIdx.x * blockDim.x + threadIdx.x;
    if (i < N) {
        int4 cc = ((const int4*)coords)[i];          // (b,z,y,x)
        int b = cc.x, y = cc.z, x = cc.w;
        int w0 = b * 1600 + ((x + 12) / 12) * 40 + ((y + 12) / 12);
        int w1 = b * 1600 + ((x + 6)  / 12) * 40 + ((y + 6)  / 12);
        g_winc0[i] = w0;
        g_winc1[i] = w1;
        int pos = atomicAdd(&g_cnt0[w0], 1);
        if (pos < CAP) g_bkt0[w0 * CAP + pos] = i;
    }
}

// ---------------- phase 2: rank round 0 + dl0 + scatter to round-1 buckets --
// rank = number of bucket entries with smaller voxel index (stable).
// Resets g_cnt0[w]=0 at the end (zero-invariant for next replay).
__global__ void __launch_bounds__(64)
k_wrank0s1() {
    __shared__ int s[CAP];
    int w = blockIdx.x;
    int n = g_cnt0[w];
    if (n > CAP) n = CAP;
    for (int t = threadIdx.x; t < n; t += 64) s[t] = g_bkt0[w * CAP + t];
    __syncthreads();
    int lvl, target; lvl_target(n, lvl, target);
    for (int e = threadIdx.x; e < n; e += 64) {
        int my = s[e];
        int r = 0;
        for (int j = 0; j < n; j++) r += (s[j] < my);
        g_inner0[my] = r;
        g_dl0[my] = (signed char)lvl;
        int kp = (r < target);
        g_keep0[my] = kp;
        if (kp) {
            int w1 = g_winc1[my];
            int pos = atomicAdd(&g_cnt1[w1], 1);
            if (pos < CAP) g_bkt1[w1 * CAP + pos] = my;
        } else {
            g_inner1[my] = -1;
            g_dl1[my]    = -1;
            g_keepF[my]  = 0;
        }
    }
    if (threadIdx.x == 0) g_cnt0[w] = 0;   // restore zero-invariant
}

// ---------------- phase 3: per-window stable rank (round 1) + dl1 -----------
__global__ void __launch_bounds__(64)
k_wrank1() {
    __shared__ int s[CAP];
    int w = blockIdx.x;
    int n = g_cnt1[w];
    if (n > CAP) n = CAP;
    for (int t = threadIdx.x; t < n; t += 64) s[t] = g_bkt1[w * CAP + t];
    __syncthreads();
    int lvl, target; lvl_target(n, lvl, target);
    for (int e = threadIdx.x; e < n; e += 64) {
        int my = s[e];
        int r = 0;
        for (int j = 0; j < n; j++) r += (s[j] < my);
        g_inner1[my] = r;
        g_dl1[my] = (signed char)lvl;
        g_keepF[my] = (r < target) ? 1 : 0;
    }
    if (threadIdx.x == 0) g_cnt1[w] = 0;   // restore zero-invariant
}

// ---------------- bulk kernel 1: positional embeddings, SHORT blocks --------
// One block = exactly 4 rows (warp per row). Short blocks recycle SM slots
// constantly so the concurrent (cheap) aux chain co-schedules under it.
__global__ void __launch_bounds__(128)
k_pe4(const int* __restrict__ coords, float* __restrict__ out, int N,
      size_t off_pe0, size_t off_pe1) {
    int warp = threadIdx.x >> 5, lane = threadIdx.x & 31;
    int i = blockIdx.x * 4 + warp;
    if (i >= N) return;
    int t = lane & 15;
    float rec0 = exp2f(-(float)(2 * t)     * KLOG);
    float rec1 = exp2f(-(float)(2 * t + 1) * KLOG);

    int x = __ldg(&coords[i * 4 + 3]);
    int y = __ldg(&coords[i * 4 + 2]);
    int v = (lane < 16) ? x : y;
    float v0 = (float)(v % 12) - 6.0f;
    float v1 = (float)((v + 6) % 12) - 6.0f;

    float4 p0, p1; float a;
    a = v0 * rec0; p0.x = __sinf(a); p0.y = __cosf(a);
    a = v0 * rec1; p0.z = __sinf(a); p0.w = __cosf(a);
    a = v1 * rec0; p1.x = __sinf(a); p1.y = __cosf(a);
    a = v1 * rec1; p1.z = __sinf(a); p1.w = __cosf(a);

    size_t row4 = (size_t)i * 32 + lane;
    ((float4*)(out + off_pe0))[row4] = p0;
    ((float4*)(out + off_pe1))[row4] = p1;
}

// ---------------- bulk kernel 2: feat mask (vector) + scalar vectors --------
// Blocks [0,Gv): warp-per-row float4 feat masking (grid-stride).
// Blocks [Gv,..): flat one-thread-per-voxel scalar outputs (pure flat reads;
// dl0/dl1 precomputed in the wrank kernels — no dependent gathers).
// Runs ALONE (after PE completes): measured 47us @ 5.7 TB/s solo.
__global__ void __launch_bounds__(128)
k_featvec(const float* __restrict__ feat, float* __restrict__ out, int N, int Gv,
          size_t off_keep, size_t off_w0, size_t off_w1,
          size_t off_dl0, size_t off_dl1, size_t off_i0, size_t off_i1) {
    if (blockIdx.x < (unsigned)Gv) {
        int warp = threadIdx.x >> 5, lane = threadIdx.x & 31;
        for (int i = blockIdx.x * 4 + warp; i < N; i += Gv * 4) {
            float kf = g_keepF[i] ? 1.0f : 0.0f;
            size_t row4 = (size_t)i * 32 + lane;
            float4 f = ((const float4*)feat)[row4];
            f.x *= kf; f.y *= kf; f.z *= kf; f.w *= kf;
            ((float4*)out)[row4] = f;
        }
    } else {
        int nb = gridDim.x - Gv;
        for (int i = (blockIdx.x - Gv) * 128 + threadIdx.x; i < N; i += nb * 128) {
            out[off_keep + i] = g_keepF[i] ? 1.0f : 0.0f;
            out[off_w0 + i]   = (float)(2 * g_winc0[i]);
            out[off_w1 + i]   = (float)(2 * g_winc1[i]);
            out[off_dl0 + i]  = (float)g_dl0[i];
            out[off_dl1 + i]  = (float)g_dl1[i];
            out[off_i0 + i]   = (float)g_inner0[i];
            out[off_i1 + i]   = (float)g_inner1[i];
        }
    }
}

// ---------------- launch ----------------
extern "C" void kernel_launch(void* const* d_in, const int* in_sizes, int n_in,
                              void* d_out, int out_size) {
    const float* feat   = (const float*)d_in[0];
    const int*   coords = (const int*)d_in[1];
    int N = in_sizes[1] / 4;
    int C = in_sizes[0] / N;          // 128 (layout constants assume this)
    if (N > MAXN) N = MAXN;

    float* out = (float*)d_out;
    size_t Ns = (size_t)N, Cs = (size_t)C;
    size_t off = Ns * Cs;             // feat at 0
    size_t off_keep = off; off += Ns;
    size_t off_w0   = off; off += Ns;
    size_t off_w1   = off; off += Ns;
    size_t off_dl0  = off; off += Ns;
    size_t off_dl1  = off; off += Ns;
    size_t off_i0   = off; off += Ns;
    size_t off_i1   = off; off += Ns;
    size_t off_pe0  = off; off += Ns * Cs;
    size_t off_pe1  = off;

    // NEW schedule: the two BULK kernels are SERIALIZED on stream0 (concurrent
    // bulk write-streams measured slower than solo-rate serial execution).
    // Only the cheap aux chain (<3% DRAM) runs concurrently, hidden under PE.
    int prLow = 0, prHigh = 0;
    cudaDeviceGetStreamPriorityRange(&prLow, &prHigh);
    cudaStream_t s2;
    cudaStreamCreateWithPriority(&s2, cudaStreamNonBlocking, prHigh);
    cudaEvent_t eFork, eMid;
    cudaEventCreateWithFlags(&eFork, cudaEventDisableTiming);
    cudaEventCreateWithFlags(&eMid,  cudaEventDisableTiming);

    cudaEventRecord(eFork, 0);
    cudaStreamWaitEvent(s2, eFork, 0);

    // aux chain (s2, high prio): finishes (~34us) well inside PE's runtime
    k_scatter0<<<(N + 255) / 256, 256, 0, s2>>>(coords, N);
    k_wrank0s1<<<NWc, 64, 0, s2>>>();
    k_wrank1<<<NWc, 64, 0, s2>>>();
    cudaEventRecord(eMid, s2);        // keepF/inner/dl all ready

    // stream0: PE solo, then featvec solo (gated on aux completion)
    k_pe4<<<(N + 3) / 4, 128>>>(coords, out, N, off_pe0, off_pe1);
    cudaStreamWaitEvent(0, eMid, 0);
    int Gv = 1184;                    // vector blocks; + 592 scalar blocks
    k_featvec<<<Gv + 592, 128>>>(feat, out, N, Gv,
                                 off_keep, off_w0, off_w1,
                                 off_dl0, off_dl1, off_i0, off_i1);
    // (featvec is the last node on stream0 — no join event needed; s2's work
    // is upstream of featvec via eMid.)
    // s2/events deliberately not destroyed: destroying capture-participating
    // resources invalidates the capture; kernel_launch runs only a few times.
}